// round 1
// baseline (speedup 1.0000x reference)
#include <cuda_runtime.h>
#include <cuda_bf16.h>
#include <cstdint>

// OverlapPatchEmbed: x (B=64, C=3, H=224, W=224) f32, patch=16, stride=8, n=27
// out (B, n*n=729, C, 256) f32
// out[b][pi*27+pj][c][r*16+s] = x[b][c][pi*8+r][pj*8+s]
//
// Pure data movement. One thread per float4 (4 consecutive s values):
// both input and output addresses are 16B aligned, so LDG.128 + STG.128.

namespace {
constexpr int B  = 64;
constexpr int C  = 3;
constexpr int H  = 224;
constexpr int W  = 224;
constexpr int PS = 16;     // patch size
constexpr int ST = 8;      // stride
constexpr int N  = 27;     // patches per dim
constexpr int NP = N * N;  // 729

// float4 counts
constexpr int V_PER_ROW   = PS / 4;              // 4 float4 per 16-float row
constexpr int V_PER_PATCH = PS * V_PER_ROW;      // 64 float4 per (c,patch) plane... per c
constexpr int V_PER_CP    = C * V_PER_PATCH;     // 192 per patch across channels
constexpr long long TOTAL_V = (long long)B * NP * V_PER_CP;  // 8,957,952
}

__global__ __launch_bounds__(256)
void overlap_patch_kernel(const float4* __restrict__ x, float4* __restrict__ out)
{
    // exact grid: one thread = one float4 of output
    long long v = (long long)blockIdx.x * blockDim.x + threadIdx.x;

    int s4 = (int)(v & 3);                 // which float4 within the 16-float row
    int t  = (int)(v >> 2);
    int r  = t & 15;            t >>= 4;   // row within patch (0..15)
    int c  = t % C;             t /= C;    // channel
    int p  = t % NP;            t /= NP;   // patch index
    int b  = t;                            // batch
    int pi = p / N;
    int pj = p - pi * N;

    // input float4 index: x is (B,C,H,W) contiguous; W=224 floats = 56 float4 per row
    int in_row  = pi * ST + r;
    int in_col4 = (pj * ST) / 4 + s4;      // pj*8 is a multiple of 4 -> aligned
    long long in_idx = (((long long)(b * C + c) * H + in_row) * (W / 4)) + in_col4;

    out[v] = __ldg(&x[in_idx]);
}

extern "C" void kernel_launch(void* const* d_in, const int* in_sizes, int n_in,
                              void* d_out, int out_size)
{
    const float4* x = (const float4*)d_in[0];
    float4* out = (float4*)d_out;

    const int threads = 256;
    const long long blocks = TOTAL_V / threads;   // 8,957,952 / 256 = 34,992 exact
    overlap_patch_kernel<<<(int)blocks, threads>>>(x, out);
}

// round 2
// speedup vs baseline: 1.2761x; 1.2761x over previous
#include <cuda_runtime.h>
#include <cuda_bf16.h>
#include <cstdint>

// OverlapPatchEmbed: x (B=64, C=3, H=224, W=224) f32, patch=16, stride=8, n=27
// out (B, 729, C, 256) f32
// out[b][pi*27+pj][c][r*16+s] = x[b][c][pi*8+r][pj*8+s]
//
// Pure data movement. One thread handles 4 float4s at stride TOTAL_THREADS:
// per-instruction coalescing is identical to the 1-elem/thread version
// (fully coalesced LDG.128/STG.128), but MLP per thread is 4, hiding
// DRAM/L2 latency without relying purely on occupancy.

namespace {
constexpr int B  = 64;
constexpr int C  = 3;
constexpr int H  = 224;
constexpr int W  = 224;
constexpr int PS = 16;     // patch size
constexpr int ST = 8;      // stride
constexpr int N  = 27;     // patches per dim
constexpr int NP = N * N;  // 729

constexpr int TOTAL_V  = B * NP * C * PS * (PS / 4);  // 8,957,952 float4s
constexpr int UNROLL   = 4;
constexpr int NTHREADS = TOTAL_V / UNROLL;            // 2,239,488
constexpr int TPB      = 256;
constexpr int NBLOCKS  = NTHREADS / TPB;              // 8,748 exact
}

__global__ __launch_bounds__(TPB)
void overlap_patch_kernel(const float4* __restrict__ x, float4* __restrict__ out)
{
    const int tid = blockIdx.x * TPB + threadIdx.x;

    float4 vals[UNROLL];

    #pragma unroll
    for (int k = 0; k < UNROLL; k++) {
        int v  = tid + k * NTHREADS;       // output float4 index
        int s4 = v & 3;                    // float4 within 16-float row
        int t  = v >> 2;
        int r  = t & 15;        t >>= 4;   // row within patch
        int c  = t % C;         t /= C;    // channel
        int p  = t % NP;        t /= NP;   // patch index
        int b  = t;                        // batch
        int pi = p / N;
        int pj = p - pi * N;

        int in_row  = pi * ST + r;
        int in_col4 = pj * (ST / 4) + s4;  // pj*8 floats -> pj*2 float4, aligned
        int in_idx  = ((b * C + c) * H + in_row) * (W / 4) + in_col4;

        vals[k] = __ldg(&x[in_idx]);
    }

    #pragma unroll
    for (int k = 0; k < UNROLL; k++) {
        out[tid + k * NTHREADS] = vals[k];
    }
}

extern "C" void kernel_launch(void* const* d_in, const int* in_sizes, int n_in,
                              void* d_out, int out_size)
{
    const float4* x = (const float4*)d_in[0];
    float4* out = (float4*)d_out;
    overlap_patch_kernel<<<NBLOCKS, TPB>>>(x, out);
}

// round 3
// speedup vs baseline: 1.3576x; 1.0639x over previous
#include <cuda_runtime.h>
#include <cuda_bf16.h>
#include <cstdint>

// OverlapPatchEmbed: x (B=64, C=3, H=224, W=224) f32 -> out (B, 729, C, 256) f32
// out[b][pi*27+pj][c][r*16+s] = x[b][c][pi*8+r][pj*8+s]
//
// Smem-staged version: block = (b, c, pi). The 16 rows of a band are one
// contiguous 14336-float region -> load is a linear coalesced copy into smem.
// Store phase writes all 27 patches of the band, fully coalesced, reading
// smem with a 240-float row pitch (mod-32 == 16) for conflict-free LDS.128.

namespace {
constexpr int B  = 64;
constexpr int C  = 3;
constexpr int H  = 224;
constexpr int W  = 224;   // 56 float4 per row
constexpr int N  = 27;
constexpr int TPB = 256;

constexpr int W4      = W / 4;          // 56 float4 per input row
constexpr int ROWS    = 16;             // rows per band
constexpr int LOAD_V  = ROWS * W4;      // 896 float4 to load per block
constexpr int PITCH4  = 60;             // smem row pitch in float4 (240 floats, mod32=16)
constexpr int STORE_V = N * 64;         // 1728 float4 to store per block (27 patches x 64)
constexpr int NBLOCKS = B * C * N;      // 5184
}

__global__ __launch_bounds__(TPB)
void overlap_patch_kernel(const float4* __restrict__ x, float4* __restrict__ out)
{
    __shared__ float4 s[ROWS * PITCH4];   // 15360 bytes

    const int bx = blockIdx.x;
    const int pi = bx % N;
    const int c  = (bx / N) % C;
    const int b  = bx / (N * C);
    const int tid = threadIdx.x;

    // ---- load phase: contiguous gmem region -> padded smem ----
    const int in_base = ((b * C + c) * H + pi * 8) * W4;   // float4 index
    #pragma unroll
    for (int k = 0; k < LOAD_V / TPB + 1; k++) {           // 896/256 -> 3.5, 4 iters
        int i = tid + k * TPB;
        if (i < LOAD_V) {
            int row = i / W4;
            int col = i - row * W4;
            s[row * PITCH4 + col] = __ldg(&x[in_base + i]);
        }
    }
    __syncthreads();

    // ---- store phase: smem -> coalesced output ----
    // out float4 index for (pj, q): ob0 + pj*192 + q, q = r*4 + s4
    const int ob0 = ((b * (N * N) + pi * N) * C + c) * 64;
    #pragma unroll
    for (int k = 0; k < STORE_V / TPB + 1; k++) {          // 1728/256 -> 6.75, 7 iters
        int j = tid + k * TPB;
        if (j < STORE_V) {
            int pj = j >> 6;
            int q  = j & 63;
            int r  = q >> 2;
            int s4 = q & 3;
            out[ob0 + pj * (C * 64) + q] = s[r * PITCH4 + pj * 2 + s4];
        }
    }
}

extern "C" void kernel_launch(void* const* d_in, const int* in_sizes, int n_in,
                              void* d_out, int out_size)
{
    const float4* x = (const float4*)d_in[0];
    float4* out = (float4*)d_out;
    overlap_patch_kernel<<<NBLOCKS, TPB>>>(x, out);
}